// round 4
// baseline (speedup 1.0000x reference)
#include <cuda_runtime.h>

#define NP 800000
#define EPS 1e-5f
typedef unsigned long long u64;

// ---------------- global scratch ----------------
__device__ float g_h1[(size_t)NP * 64];    // stage-1 POST bn+relu
__device__ float g_Y2[(size_t)NP * 64];    // conv pre-BN (raw)
__device__ int2  g_list[8][NP];            // per-offset compacted (out, src)
__device__ int   g_cnt[8];
__device__ float g_stats[128];             // Y2: sum[0,64) sq[64,128)
__device__ float g_C[4096];                // 64x64 second-moment (raw sums)
__device__ float g_Csum[64];               // column sums
// scale/shift: Y1 @0..64, YS @64..320, h2 @320..384, Y3 @384..640
__device__ float g_scale[640];
__device__ float g_shift[640];

// ---------------- f32x2 helpers ----------------
__device__ __forceinline__ void ffma2(u64 &acc, u64 x, u64 w) {
    asm("fma.rn.f32x2 %0, %1, %2, %0;" : "+l"(acc) : "l"(x), "l"(w));
}
__device__ __forceinline__ u64 pack2(float a, float b) {
    u64 r; asm("mov.b64 %0, {%1, %2};" : "=l"(r)
               : "r"(__float_as_uint(a)), "r"(__float_as_uint(b))); return r;
}
__device__ __forceinline__ u64 dup2(float v) {
    u64 r; asm("mov.b64 %0, {%1, %1};" : "=l"(r) : "r"(__float_as_uint(v))); return r;
}
__device__ __forceinline__ float2 unpack2(u64 v) {
    unsigned lo, hi; asm("mov.b64 {%0, %1}, %2;" : "=r"(lo), "=r"(hi) : "l"(v));
    return make_float2(__uint_as_float(lo), __uint_as_float(hi));
}

// dot of x-row (32 packed pairs = 64 floats) with 4 transposed-weight columns.
// WT[c*64 + j]: all lanes read the same address -> broadcast LDS.
__device__ __forceinline__ float4 dot4(const float* __restrict__ WT,
                                       const u64* __restrict__ xp, int c) {
    const ulonglong2* w0 = (const ulonglong2*)(WT + (c + 0) * 64);
    const ulonglong2* w1 = (const ulonglong2*)(WT + (c + 1) * 64);
    const ulonglong2* w2 = (const ulonglong2*)(WT + (c + 2) * 64);
    const ulonglong2* w3 = (const ulonglong2*)(WT + (c + 3) * 64);
    u64 a0 = 0, a1 = 0, a2 = 0, a3 = 0;
#pragma unroll
    for (int m = 0; m < 16; m++) {
        ulonglong2 v0 = w0[m]; ffma2(a0, xp[2*m], v0.x); ffma2(a0, xp[2*m+1], v0.y);
        ulonglong2 v1 = w1[m]; ffma2(a1, xp[2*m], v1.x); ffma2(a1, xp[2*m+1], v1.y);
        ulonglong2 v2 = w2[m]; ffma2(a2, xp[2*m], v2.x); ffma2(a2, xp[2*m+1], v2.y);
        ulonglong2 v3 = w3[m]; ffma2(a3, xp[2*m], v3.x); ffma2(a3, xp[2*m+1], v3.y);
    }
    float2 p0 = unpack2(a0), p1 = unpack2(a1), p2 = unpack2(a2), p3 = unpack2(a3);
    return make_float4(p0.x + p0.y, p1.x + p1.y, p2.x + p2.y, p3.x + p3.y);
}

__global__ void zero_kernel(int mode) {
    int i = blockIdx.x * blockDim.x + threadIdx.x;
    if (i < 4096) g_C[i] = 0.f;
    if (i < 64) g_Csum[i] = 0.f;
    if (mode == 0) {
        if (i < 128) g_stats[i] = 0.f;
        if (i < 8) g_cnt[i] = 0;
    }
}

// ---------------- SYRK: C += X^T X, Csum += colsums(X) over 64-wide rows ----------------
// which=0: X = Xin (feats, raw). which=1: X = bnrelu(g_Y2) with scale/shift @320.
// grid 250 blocks x 3200 rows.
__global__ __launch_bounds__(256) void syrk_kernel(const float* __restrict__ Xin, int which) {
    __shared__ float tile[32 * 64];
    __shared__ float sc[64], sh[64];
    int t = threadIdx.x;
    if (which && t < 64) { sc[t] = g_scale[320 + t]; sh[t] = g_shift[320 + t]; }
    int ta = t >> 4, tb = t & 15;
    u64 acc[8] = {0,0,0,0,0,0,0,0};
    float cs0 = 0.f, cs1 = 0.f, cs2 = 0.f, cs3 = 0.f;
    const float4* src = (const float4*)(which ? (const float*)g_Y2 : Xin);
    long base16 = (long)blockIdx.x * 3200 * 16;   // float4 index of block start

    for (int t0 = 0; t0 < 3200; t0 += 32) {
        __syncthreads();
        for (int i = t; i < 512; i += 256) {
            float4 v = src[base16 + (long)t0 * 16 + i];
            if (which) {
                int c0 = (i & 15) * 4;
                float4 s = *(const float4*)(sc + c0);
                float4 h = *(const float4*)(sh + c0);
                v.x = fmaxf(fmaf(v.x, s.x, h.x), 0.f);
                v.y = fmaxf(fmaf(v.y, s.y, h.y), 0.f);
                v.z = fmaxf(fmaf(v.z, s.z, h.z), 0.f);
                v.w = fmaxf(fmaf(v.w, s.w, h.w), 0.f);
            }
            *(float4*)(tile + i * 4) = v;
        }
        __syncthreads();
#pragma unroll 4
        for (int r = 0; r < 32; r++) {
            float4 xa = *(const float4*)(tile + r * 64 + ta * 4);
            float4 xb = *(const float4*)(tile + r * 64 + tb * 4);
            u64 b01 = pack2(xb.x, xb.y), b23 = pack2(xb.z, xb.w);
            u64 d;
            d = dup2(xa.x); ffma2(acc[0], d, b01); ffma2(acc[1], d, b23);
            d = dup2(xa.y); ffma2(acc[2], d, b01); ffma2(acc[3], d, b23);
            d = dup2(xa.z); ffma2(acc[4], d, b01); ffma2(acc[5], d, b23);
            d = dup2(xa.w); ffma2(acc[6], d, b01); ffma2(acc[7], d, b23);
            if (tb == 0) { cs0 += xa.x; cs1 += xa.y; cs2 += xa.z; cs3 += xa.w; }
        }
    }
#pragma unroll
    for (int a = 0; a < 4; a++) {
        float2 p0 = unpack2(acc[a * 2]), p1 = unpack2(acc[a * 2 + 1]);
        int row = ta * 4 + a;
        atomicAdd(&g_C[row * 64 + tb * 4 + 0], p0.x);
        atomicAdd(&g_C[row * 64 + tb * 4 + 1], p0.y);
        atomicAdd(&g_C[row * 64 + tb * 4 + 2], p1.x);
        atomicAdd(&g_C[row * 64 + tb * 4 + 3], p1.y);
    }
    if (tb == 0) {
        atomicAdd(&g_Csum[ta * 4 + 0], cs0);
        atomicAdd(&g_Csum[ta * 4 + 1], cs1);
        atomicAdd(&g_Csum[ta * 4 + 2], cs2);
        atomicAdd(&g_Csum[ta * 4 + 3], cs3);
    }
}

// ---------------- analytic BN params for a linear layer y = x@W + b ----------------
// scale = gamma*rsqrt(var+eps), shift = beta - mu_s*scale  (bias folds out; GEMM adds no bias)
__global__ void prep_kernel(const float* __restrict__ W, const float* __restrict__ bias,
                            const float* __restrict__ gamma, const float* __restrict__ beta,
                            int ncols, int outOff) {
    __shared__ float Cs[4096];
    __shared__ float m[64];
    int t = threadIdx.x;
    float invN = 1.0f / (float)NP;
    for (int i = t; i < 4096; i += blockDim.x) Cs[i] = g_C[i] * invN;
    if (t < 64) m[t] = g_Csum[t] * invN;
    __syncthreads();
    if (t < ncols) {
        float w[64];
#pragma unroll
        for (int a = 0; a < 64; a++) w[a] = W[a * ncols + t];
        float mu = 0.f;
#pragma unroll
        for (int a = 0; a < 64; a++) mu = fmaf(m[a], w[a], mu);
        float q = 0.f;
#pragma unroll
        for (int a = 0; a < 64; a++) {
            const float* Cr = Cs + a * 64;
            float d0 = 0.f, d1 = 0.f, d2 = 0.f, d3 = 0.f;
#pragma unroll
            for (int b = 0; b < 64; b += 4) {
                d0 = fmaf(Cr[b + 0], w[b + 0], d0);
                d1 = fmaf(Cr[b + 1], w[b + 1], d1);
                d2 = fmaf(Cr[b + 2], w[b + 2], d2);
                d3 = fmaf(Cr[b + 3], w[b + 3], d3);
            }
            q = fmaf(w[a], (d0 + d1) + (d2 + d3), q);
        }
        (void)bias;  // bias does not affect scale/shift (folds out)
        float var = q - mu * mu;
        float scv = rsqrtf(var + EPS) * gamma[t];
        g_scale[outOff + t] = scv;
        g_shift[outOff + t] = beta[t] - mu * scv;
    }
}

// ---------------- GEMM1: h1 = relu(bn(feats@w1)) ; out = bn(feats@ws) ----------------
__global__ __launch_bounds__(256) void gemm1_kernel(
    const float* __restrict__ feats, const float* __restrict__ w1,
    const float* __restrict__ ws, float* __restrict__ outYS) {
    extern __shared__ float sm[];
    float* WT = sm;               // 320 cols x 64 (transposed)
    float* scA = sm + 20480;      // 320
    float* shA = sm + 20800;      // 320
    int t = threadIdx.x;
    for (int i = t; i < 20480; i += 256) {
        int c = i >> 6, j = i & 63;
        WT[i] = (c < 64) ? w1[j * 64 + c] : ws[j * 256 + (c - 64)];
    }
    for (int i = t; i < 320; i += 256) { scA[i] = g_scale[i]; shA[i] = g_shift[i]; }
    __syncthreads();

    long row = (long)blockIdx.x * 256 + t;
    u64 xp[32];
    const ulonglong2* xr = (const ulonglong2*)(feats + row * 64);
#pragma unroll
    for (int m = 0; m < 16; m++) { ulonglong2 v = xr[m]; xp[2*m] = v.x; xp[2*m+1] = v.y; }
    float* h1r = g_h1 + row * 64;
    float* ysr = outYS + row * 256;
#pragma unroll 1
    for (int cq = 0; cq < 80; cq++) {
        int c = cq * 4;
        float4 r = dot4(WT, xp, c);
        float4 s = *(const float4*)(scA + c);
        float4 h = *(const float4*)(shA + c);
        if (c < 64) {
            r.x = fmaxf(fmaf(r.x, s.x, h.x), 0.f);
            r.y = fmaxf(fmaf(r.y, s.y, h.y), 0.f);
            r.z = fmaxf(fmaf(r.z, s.z, h.z), 0.f);
            r.w = fmaxf(fmaf(r.w, s.w, h.w), 0.f);
            *(float4*)(h1r + c) = r;
        } else {
            r.x = fmaf(r.x, s.x, h.x); r.y = fmaf(r.y, s.y, h.y);
            r.z = fmaf(r.z, s.z, h.z); r.w = fmaf(r.w, s.w, h.w);
            *(float4*)(ysr + (c - 64)) = r;
        }
    }
}

// ---------------- direct column stats for Y2 ----------------
__global__ __launch_bounds__(256) void stats2_kernel() {
    __shared__ float s[128];
    int t = threadIdx.x;
    for (int i = t; i < 128; i += 256) s[i] = 0.f;
    __syncthreads();
    int cg = t & 15;                         // 16 col-groups of 4
    long r = (long)blockIdx.x * 16 + (t >> 4);
    long stride = (long)gridDim.x * 16;
    float s0=0,s1=0,s2=0,s3=0,q0=0,q1=0,q2=0,q3=0;
    for (; r < NP; r += stride) {
        float4 v = *(const float4*)(g_Y2 + r * 64 + cg * 4);
        s0 += v.x; q0 = fmaf(v.x, v.x, q0);
        s1 += v.y; q1 = fmaf(v.y, v.y, q1);
        s2 += v.z; q2 = fmaf(v.z, v.z, q2);
        s3 += v.w; q3 = fmaf(v.w, v.w, q3);
    }
    int c = cg * 4;
    atomicAdd(&s[c+0], s0); atomicAdd(&s[c+1], s1);
    atomicAdd(&s[c+2], s2); atomicAdd(&s[c+3], s3);
    atomicAdd(&s[64+c+0], q0); atomicAdd(&s[64+c+1], q1);
    atomicAdd(&s[64+c+2], q2); atomicAdd(&s[64+c+3], q3);
    __syncthreads();
    for (int i = t; i < 128; i += 256) atomicAdd(&g_stats[i], s[i]);
}

__global__ void finalize2_kernel(const float* __restrict__ gamma, const float* __restrict__ beta) {
    int t = threadIdx.x;
    if (t < 64) {
        float inv = 1.0f / (float)NP;
        float m = g_stats[t] * inv;
        float v = g_stats[64 + t] * inv - m * m;
        float sc = rsqrtf(v + EPS) * gamma[t];
        g_scale[320 + t] = sc;
        g_shift[320 + t] = beta[t] - m * sc;
    }
}

// ---------------- compaction: per-offset (out, src) lists ----------------
__global__ __launch_bounds__(256) void compact_kernel(const int* __restrict__ nbrs) {
    __shared__ int scnt[8], sbase[8], woff[8][8];
    int t = threadIdx.x, w = t >> 5, lane = t & 31;
    if (t < 8) scnt[t] = 0;
    __syncthreads();
    int i = blockIdx.x * 256 + t;  // grid 3125 * 256 == NP exactly
    int nb[8];
    {
        int kk = 0;
#pragma unroll
        for (int k = 0; k < 9; k++) {
            if (k == 4) continue;
            nb[kk++] = nbrs[i * 9 + k];
        }
    }
    unsigned ball[8];
#pragma unroll
    for (int k = 0; k < 8; k++) {
        unsigned m = __ballot_sync(0xffffffffu, nb[k] >= 0);
        ball[k] = m;
        if (lane == 0) woff[k][w] = atomicAdd(&scnt[k], __popc(m));
    }
    __syncthreads();
    if (t < 8) sbase[t] = atomicAdd(&g_cnt[t], scnt[t]);
    __syncthreads();
#pragma unroll
    for (int k = 0; k < 8; k++) {
        if (nb[k] >= 0) {
            int r = __popc(ball[k] & ((1u << lane) - 1u));
            g_list[k][sbase[k] + woff[k][w] + r] = make_int2(i, nb[k]);
        }
    }
}

// ---------------- conv center tap: Y2 = b2 + h1 @ w2[4] ----------------
__global__ __launch_bounds__(256) void conv_center_kernel(
    const float* __restrict__ w2, const float* __restrict__ b2) {
    extern __shared__ float sm[];
    float* WT = sm;            // 64x64 transposed
    float* bias = sm + 4096;   // 64
    int t = threadIdx.x;
    for (int i = t; i < 4096; i += 256) {
        int c = i >> 6, j = i & 63;
        WT[i] = w2[4 * 4096 + j * 64 + c];
    }
    if (t < 64) bias[t] = b2[t];
    __syncthreads();

    long row = (long)blockIdx.x * 256 + t;
    u64 xp[32];
    const ulonglong2* xr = (const ulonglong2*)(g_h1 + row * 64);
#pragma unroll
    for (int m = 0; m < 16; m++) { ulonglong2 v = xr[m]; xp[2*m] = v.x; xp[2*m+1] = v.y; }
    float* yr = g_Y2 + row * 64;
#pragma unroll 1
    for (int cq = 0; cq < 16; cq++) {
        int c = cq * 4;
        float4 r = dot4(WT, xp, c);
        r.x += bias[c]; r.y += bias[c+1]; r.z += bias[c+2]; r.w += bias[c+3];
        *(float4*)(yr + c) = r;
    }
}

// ---------------- conv non-center tap kk (8 sequential launches) ----------------
__global__ __launch_bounds__(256) void convk_kernel(const float* __restrict__ w2, int kk) {
    extern __shared__ float sm[];
    float* WT = sm;           // 64x64 transposed
    int tap = (kk < 4) ? kk : kk + 1;
    int t = threadIdx.x;
    for (int i = t; i < 4096; i += 256) {
        int c = i >> 6, j = i & 63;
        WT[i] = w2[tap * 4096 + j * 64 + c];
    }
    __syncthreads();

    int n = g_cnt[kk];
    for (long e = (long)blockIdx.x * 256 + t; e < n; e += (long)gridDim.x * 256) {
        int2 ent = g_list[kk][e];
        u64 xp[32];
        const ulonglong2* xr = (const ulonglong2*)(g_h1 + (long)ent.y * 64);
#pragma unroll
        for (int m = 0; m < 16; m++) { ulonglong2 v = xr[m]; xp[2*m] = v.x; xp[2*m+1] = v.y; }
        float* yr = g_Y2 + (long)ent.x * 64;
#pragma unroll 1
        for (int cq = 0; cq < 16; cq++) {
            int c = cq * 4;
            float4 r = dot4(WT, xp, c);
            float4 y = *(float4*)(yr + c);
            y.x += r.x; y.y += r.y; y.z += r.z; y.w += r.w;
            *(float4*)(yr + c) = y;
        }
    }
}

// ---------------- GEMM3+final: out += relu(bn(bnrelu(Y2) @ w3)) ----------------
__global__ __launch_bounds__(256) void gemm3_kernel(
    const float* __restrict__ w3, float* __restrict__ out) {
    extern __shared__ float sm[];
    float* WT  = sm;              // 256 cols x 64 transposed
    float* sc2 = sm + 16384;      // 64
    float* sh2 = sm + 16448;      // 64
    float* sc3 = sm + 16512;      // 256
    float* sh3 = sm + 16768;      // 256
    int t = threadIdx.x;
    for (int i = t; i < 16384; i += 256) {
        int c = i >> 6, j = i & 63;
        WT[i] = w3[j * 256 + c];
    }
    if (t < 64) { sc2[t] = g_scale[320 + t]; sh2[t] = g_shift[320 + t]; }
    for (int i = t; i < 256; i += 256) { sc3[i] = g_scale[384 + i]; sh3[i] = g_shift[384 + i]; }
    __syncthreads();

    long row = (long)blockIdx.x * 256 + t;
    u64 xp[32];
    {
        const float* r2 = g_Y2 + row * 64;
#pragma unroll
        for (int m = 0; m < 16; m++) {
            float4 v = *(const float4*)(r2 + 4 * m);
            float4 s = *(const float4*)(sc2 + 4 * m);
            float4 h = *(const float4*)(sh2 + 4 * m);
            float x0 = fmaxf(fmaf(v.x, s.x, h.x), 0.f);
            float x1 = fmaxf(fmaf(v.y, s.y, h.y), 0.f);
            float x2 = fmaxf(fmaf(v.z, s.z, h.z), 0.f);
            float x3 = fmaxf(fmaf(v.w, s.w, h.w), 0.f);
            xp[2*m] = pack2(x0, x1); xp[2*m+1] = pack2(x2, x3);
        }
    }
    float* yr = out + row * 256;
#pragma unroll 1
    for (int cq = 0; cq < 64; cq++) {
        int c = cq * 4;
        float4 r = dot4(WT, xp, c);
        float4 s = *(const float4*)(sc3 + c);
        float4 h = *(const float4*)(sh3 + c);
        float4 res = *(float4*)(yr + c);
        res.x += fmaxf(fmaf(r.x, s.x, h.x), 0.f);
        res.y += fmaxf(fmaf(r.y, s.y, h.y), 0.f);
        res.z += fmaxf(fmaf(r.z, s.z, h.z), 0.f);
        res.w += fmaxf(fmaf(r.w, s.w, h.w), 0.f);
        *(float4*)(yr + c) = res;
    }
}

extern "C" void kernel_launch(void* const* d_in, const int* in_sizes, int n_in,
                              void* d_out, int out_size) {
    const float* feats = (const float*)d_in[0];
    const int*   nbrs  = (const int*)d_in[1];
    const float* w1  = (const float*)d_in[2];
    const float* b1  = (const float*)d_in[3];
    const float* g1  = (const float*)d_in[4];
    const float* be1 = (const float*)d_in[5];
    const float* w2  = (const float*)d_in[6];
    const float* b2  = (const float*)d_in[7];
    const float* g2  = (const float*)d_in[8];
    const float* be2 = (const float*)d_in[9];
    const float* w3  = (const float*)d_in[10];
    const float* b3  = (const float*)d_in[11];
    const float* g3  = (const float*)d_in[12];
    const float* be3 = (const float*)d_in[13];
    const float* wsp = (const float*)d_in[14];
    const float* bsp = (const float*)d_in[15];
    const float* gsp = (const float*)d_in[16];
    const float* besp= (const float*)d_in[17];
    float* out = (float*)d_out;

    cudaFuncSetAttribute(gemm1_kernel, cudaFuncAttributeMaxDynamicSharedMemorySize, 87040);
    cudaFuncSetAttribute(gemm3_kernel, cudaFuncAttributeMaxDynamicSharedMemorySize, 69632);

    zero_kernel<<<16, 256>>>(0);
    // stage-1 analytic BN params from feats second moments
    syrk_kernel<<<250, 256>>>(feats, 0);
    prep_kernel<<<1, 64 >>>(w1,  b1,  g1,  be1,  64,  0);    // Y1 -> h1 params
    prep_kernel<<<1, 256>>>(wsp, bsp, gsp, besp, 256, 64);   // YS params
    gemm1_kernel<<<3125, 256, 87040>>>(feats, w1, wsp, out);
    // conv
    compact_kernel<<<3125, 256>>>(nbrs);
    conv_center_kernel<<<3125, 256, 16640>>>(w2, b2);
    for (int kk = 0; kk < 8; kk++)
        convk_kernel<<<1184, 256, 16384>>>(w2, kk);
    // Y2 stats (direct), then h2 analytic second moments -> Y3 params
    stats2_kernel<<<1184, 256>>>();
    finalize2_kernel<<<1, 64>>>(g2, be2);
    zero_kernel<<<16, 256>>>(1);
    syrk_kernel<<<250, 256>>>(nullptr, 1);
    prep_kernel<<<1, 256>>>(w3, b3, g3, be3, 256, 384);
    // fused gemm3 + BN + relu + residual add
    gemm3_kernel<<<3125, 256, 69632>>>(w3, out);
}

// round 5
// speedup vs baseline: 1.3557x; 1.3557x over previous
#include <cuda_runtime.h>

#define NP 800000
#define HNP 400000
#define EPS 1e-5f
typedef unsigned long long u64;

// ---------------- global scratch ----------------
__device__ float g_h1[(size_t)NP * 64];    // stage-1 POST bn+relu
__device__ float g_Y2[(size_t)NP * 64];    // conv pre-BN (raw)
__device__ int2  g_list[8][NP];            // per-offset compacted (out, src)
__device__ int   g_cnt[8];
__device__ float g_stats[128];             // Y2: sum[0,64) sq[64,128)
__device__ float g_C[4096];                // 64x64 second-moment (raw sums)
__device__ float g_Csum[64];               // column sums
// scale/shift: Y1 @0..64, YS @64..320, h2 @320..384, Y3 @384..640
__device__ float g_scale[640];
__device__ float g_shift[640];

// ---------------- f32x2 helpers ----------------
__device__ __forceinline__ void ffma2(u64 &acc, u64 x, u64 w) {
    asm("fma.rn.f32x2 %0, %1, %2, %0;" : "+l"(acc) : "l"(x), "l"(w));
}
__device__ __forceinline__ u64 pack2(float a, float b) {
    u64 r; asm("mov.b64 %0, {%1, %2};" : "=l"(r)
               : "r"(__float_as_uint(a)), "r"(__float_as_uint(b))); return r;
}
__device__ __forceinline__ u64 dup2(float v) {
    u64 r; asm("mov.b64 %0, {%1, %1};" : "=l"(r) : "r"(__float_as_uint(v))); return r;
}
__device__ __forceinline__ float2 unpack2(u64 v) {
    unsigned lo, hi; asm("mov.b64 {%0, %1}, %2;" : "=r"(lo), "=r"(hi) : "l"(v));
    return make_float2(__uint_as_float(lo), __uint_as_float(hi));
}

// 2-row x 4-col dot: weights loaded once, used for both rows.
// WT[c*64 + j] transposed; broadcast LDS.128 per 4 j's per column.
__device__ __forceinline__ void dot4x2(const float* __restrict__ WT,
                                       const u64* __restrict__ xa, const u64* __restrict__ xb,
                                       int c, float4& ra, float4& rb) {
    const ulonglong2* w0 = (const ulonglong2*)(WT + (c + 0) * 64);
    const ulonglong2* w1 = (const ulonglong2*)(WT + (c + 1) * 64);
    const ulonglong2* w2 = (const ulonglong2*)(WT + (c + 2) * 64);
    const ulonglong2* w3 = (const ulonglong2*)(WT + (c + 3) * 64);
    u64 a0 = 0, a1 = 0, a2 = 0, a3 = 0;
    u64 b0 = 0, b1 = 0, b2 = 0, b3 = 0;
#pragma unroll
    for (int m = 0; m < 16; m++) {
        ulonglong2 v0 = w0[m];
        ffma2(a0, xa[2*m], v0.x); ffma2(a0, xa[2*m+1], v0.y);
        ffma2(b0, xb[2*m], v0.x); ffma2(b0, xb[2*m+1], v0.y);
        ulonglong2 v1 = w1[m];
        ffma2(a1, xa[2*m], v1.x); ffma2(a1, xa[2*m+1], v1.y);
        ffma2(b1, xb[2*m], v1.x); ffma2(b1, xb[2*m+1], v1.y);
        ulonglong2 v2 = w2[m];
        ffma2(a2, xa[2*m], v2.x); ffma2(a2, xa[2*m+1], v2.y);
        ffma2(b2, xb[2*m], v2.x); ffma2(b2, xb[2*m+1], v2.y);
        ulonglong2 v3 = w3[m];
        ffma2(a3, xa[2*m], v3.x); ffma2(a3, xa[2*m+1], v3.y);
        ffma2(b3, xb[2*m], v3.x); ffma2(b3, xb[2*m+1], v3.y);
    }
    float2 p;
    p = unpack2(a0); ra.x = p.x + p.y;
    p = unpack2(a1); ra.y = p.x + p.y;
    p = unpack2(a2); ra.z = p.x + p.y;
    p = unpack2(a3); ra.w = p.x + p.y;
    p = unpack2(b0); rb.x = p.x + p.y;
    p = unpack2(b1); rb.y = p.x + p.y;
    p = unpack2(b2); rb.z = p.x + p.y;
    p = unpack2(b3); rb.w = p.x + p.y;
}

__device__ __forceinline__ void load_row(const float* __restrict__ row, u64* xp) {
    const ulonglong2* xr = (const ulonglong2*)row;
#pragma unroll
    for (int m = 0; m < 16; m++) { ulonglong2 v = xr[m]; xp[2*m] = v.x; xp[2*m+1] = v.y; }
}

__global__ void zero_kernel(int mode) {
    int i = blockIdx.x * blockDim.x + threadIdx.x;
    if (i < 4096) g_C[i] = 0.f;
    if (i < 64) g_Csum[i] = 0.f;
    if (mode == 0) {
        if (i < 128) g_stats[i] = 0.f;
        if (i < 8) g_cnt[i] = 0;
    }
}

// ---------------- SYRK: C += X^T X, Csum += colsums(X) ----------------
// which=0: X = Xin (feats). which=1: X = bnrelu(g_Y2) with scale/shift @320.
__global__ __launch_bounds__(256) void syrk_kernel(const float* __restrict__ Xin, int which) {
    __shared__ float tile[32 * 64];
    __shared__ float sc[64], sh[64];
    int t = threadIdx.x;
    if (which && t < 64) { sc[t] = g_scale[320 + t]; sh[t] = g_shift[320 + t]; }
    int ta = t >> 4, tb = t & 15;
    u64 acc[8] = {0,0,0,0,0,0,0,0};
    float cs0 = 0.f, cs1 = 0.f, cs2 = 0.f, cs3 = 0.f;
    const float4* src = (const float4*)(which ? (const float*)g_Y2 : Xin);
    long base16 = (long)blockIdx.x * 3200 * 16;

    for (int t0 = 0; t0 < 3200; t0 += 32) {
        __syncthreads();
        for (int i = t; i < 512; i += 256) {
            float4 v = src[base16 + (long)t0 * 16 + i];
            if (which) {
                int c0 = (i & 15) * 4;
                float4 s = *(const float4*)(sc + c0);
                float4 h = *(const float4*)(sh + c0);
                v.x = fmaxf(fmaf(v.x, s.x, h.x), 0.f);
                v.y = fmaxf(fmaf(v.y, s.y, h.y), 0.f);
                v.z = fmaxf(fmaf(v.z, s.z, h.z), 0.f);
                v.w = fmaxf(fmaf(v.w, s.w, h.w), 0.f);
            }
            *(float4*)(tile + i * 4) = v;
        }
        __syncthreads();
#pragma unroll 4
        for (int r = 0; r < 32; r++) {
            float4 xa = *(const float4*)(tile + r * 64 + ta * 4);
            float4 xb = *(const float4*)(tile + r * 64 + tb * 4);
            u64 b01 = pack2(xb.x, xb.y), b23 = pack2(xb.z, xb.w);
            u64 d;
            d = dup2(xa.x); ffma2(acc[0], d, b01); ffma2(acc[1], d, b23);
            d = dup2(xa.y); ffma2(acc[2], d, b01); ffma2(acc[3], d, b23);
            d = dup2(xa.z); ffma2(acc[4], d, b01); ffma2(acc[5], d, b23);
            d = dup2(xa.w); ffma2(acc[6], d, b01); ffma2(acc[7], d, b23);
            if (tb == 0) { cs0 += xa.x; cs1 += xa.y; cs2 += xa.z; cs3 += xa.w; }
        }
    }
#pragma unroll
    for (int a = 0; a < 4; a++) {
        float2 p0 = unpack2(acc[a * 2]), p1 = unpack2(acc[a * 2 + 1]);
        int row = ta * 4 + a;
        atomicAdd(&g_C[row * 64 + tb * 4 + 0], p0.x);
        atomicAdd(&g_C[row * 64 + tb * 4 + 1], p0.y);
        atomicAdd(&g_C[row * 64 + tb * 4 + 2], p1.x);
        atomicAdd(&g_C[row * 64 + tb * 4 + 3], p1.y);
    }
    if (tb == 0) {
        atomicAdd(&g_Csum[ta * 4 + 0], cs0);
        atomicAdd(&g_Csum[ta * 4 + 1], cs1);
        atomicAdd(&g_Csum[ta * 4 + 2], cs2);
        atomicAdd(&g_Csum[ta * 4 + 3], cs3);
    }
}

// ---------------- analytic BN params for y = x@W + b ----------------
__device__ __forceinline__ void prep_body(const float* __restrict__ W,
        const float* __restrict__ gamma, const float* __restrict__ beta,
        int ncols, int outOff) {
    __shared__ float Cs[4096];
    __shared__ float m[64];
    int t = threadIdx.x;
    float invN = 1.0f / (float)NP;
    for (int i = t; i < 4096; i += blockDim.x) Cs[i] = g_C[i] * invN;
    if (t < 64) m[t] = g_Csum[t] * invN;
    __syncthreads();
    if (t < ncols) {
        float w[64];
#pragma unroll
        for (int a = 0; a < 64; a++) w[a] = W[a * ncols + t];
        float mu = 0.f;
#pragma unroll
        for (int a = 0; a < 64; a++) mu = fmaf(m[a], w[a], mu);
        float q = 0.f;
#pragma unroll
        for (int a = 0; a < 64; a++) {
            const float* Cr = Cs + a * 64;
            float d0 = 0.f, d1 = 0.f, d2 = 0.f, d3 = 0.f;
#pragma unroll
            for (int b = 0; b < 64; b += 4) {
                d0 = fmaf(Cr[b + 0], w[b + 0], d0);
                d1 = fmaf(Cr[b + 1], w[b + 1], d1);
                d2 = fmaf(Cr[b + 2], w[b + 2], d2);
                d3 = fmaf(Cr[b + 3], w[b + 3], d3);
            }
            q = fmaf(w[a], (d0 + d1) + (d2 + d3), q);
        }
        float var = q - mu * mu;
        float scv = rsqrtf(var + EPS) * gamma[t];
        g_scale[outOff + t] = scv;
        g_shift[outOff + t] = beta[t] - mu * scv;
    }
}

// block 0: w1 (64 cols, outOff 0); block 1: ws (256 cols, outOff 64)
__global__ void prep_dual_kernel(const float* __restrict__ w1, const float* __restrict__ g1,
                                 const float* __restrict__ be1,
                                 const float* __restrict__ ws, const float* __restrict__ gs,
                                 const float* __restrict__ bes) {
    if (blockIdx.x == 0) prep_body(w1, g1, be1, 64, 0);
    else                 prep_body(ws, gs, bes, 256, 64);
}
__global__ void prep_kernel(const float* __restrict__ W, const float* __restrict__ gamma,
                            const float* __restrict__ beta, int ncols, int outOff) {
    prep_body(W, gamma, beta, ncols, outOff);
}

// ---------------- GEMM1 (2 rows/thread): h1 = relu(bn(feats@w1)); out = bn(feats@ws) ----------------
__global__ __launch_bounds__(256, 1) void gemm1_kernel(
    const float* __restrict__ feats, const float* __restrict__ w1,
    const float* __restrict__ ws, float* __restrict__ outYS) {
    extern __shared__ float sm[];
    float* WT = sm;               // 320 cols x 64 (transposed)
    float* scA = sm + 20480;      // 320
    float* shA = sm + 20800;      // 320
    int t = threadIdx.x;
    for (int i = t; i < 20480; i += 256) {
        int c = i >> 6, j = i & 63;
        WT[i] = (c < 64) ? w1[j * 64 + c] : ws[j * 256 + (c - 64)];
    }
    for (int i = t; i < 320; i += 256) { scA[i] = g_scale[i]; shA[i] = g_shift[i]; }
    __syncthreads();

    int idx = blockIdx.x * 256 + t;
    if (idx >= HNP) return;
    long r0 = 2L * idx, r1 = r0 + 1;
    u64 xa[32], xb[32];
    load_row(feats + r0 * 64, xa);
    load_row(feats + r1 * 64, xb);
    float* h1a = g_h1 + r0 * 64;  float* h1b = g_h1 + r1 * 64;
    float* ysa = outYS + r0 * 256; float* ysb = outYS + r1 * 256;
#pragma unroll 1
    for (int cq = 0; cq < 80; cq++) {
        int c = cq * 4;
        float4 ra, rb;
        dot4x2(WT, xa, xb, c, ra, rb);
        float4 s = *(const float4*)(scA + c);
        float4 h = *(const float4*)(shA + c);
        if (c < 64) {
            ra.x = fmaxf(fmaf(ra.x, s.x, h.x), 0.f); ra.y = fmaxf(fmaf(ra.y, s.y, h.y), 0.f);
            ra.z = fmaxf(fmaf(ra.z, s.z, h.z), 0.f); ra.w = fmaxf(fmaf(ra.w, s.w, h.w), 0.f);
            rb.x = fmaxf(fmaf(rb.x, s.x, h.x), 0.f); rb.y = fmaxf(fmaf(rb.y, s.y, h.y), 0.f);
            rb.z = fmaxf(fmaf(rb.z, s.z, h.z), 0.f); rb.w = fmaxf(fmaf(rb.w, s.w, h.w), 0.f);
            *(float4*)(h1a + c) = ra;
            *(float4*)(h1b + c) = rb;
        } else {
            ra.x = fmaf(ra.x, s.x, h.x); ra.y = fmaf(ra.y, s.y, h.y);
            ra.z = fmaf(ra.z, s.z, h.z); ra.w = fmaf(ra.w, s.w, h.w);
            rb.x = fmaf(rb.x, s.x, h.x); rb.y = fmaf(rb.y, s.y, h.y);
            rb.z = fmaf(rb.z, s.z, h.z); rb.w = fmaf(rb.w, s.w, h.w);
            *(float4*)(ysa + (c - 64)) = ra;
            *(float4*)(ysb + (c - 64)) = rb;
        }
    }
}

// ---------------- direct column stats for Y2 ----------------
__global__ __launch_bounds__(256) void stats2_kernel() {
    __shared__ float s[128];
    int t = threadIdx.x;
    for (int i = t; i < 128; i += 256) s[i] = 0.f;
    __syncthreads();
    int cg = t & 15;
    long r = (long)blockIdx.x * 16 + (t >> 4);
    long stride = (long)gridDim.x * 16;
    float s0=0,s1=0,s2=0,s3=0,q0=0,q1=0,q2=0,q3=0;
    for (; r < NP; r += stride) {
        float4 v = *(const float4*)(g_Y2 + r * 64 + cg * 4);
        s0 += v.x; q0 = fmaf(v.x, v.x, q0);
        s1 += v.y; q1 = fmaf(v.y, v.y, q1);
        s2 += v.z; q2 = fmaf(v.z, v.z, q2);
        s3 += v.w; q3 = fmaf(v.w, v.w, q3);
    }
    int c = cg * 4;
    atomicAdd(&s[c+0], s0); atomicAdd(&s[c+1], s1);
    atomicAdd(&s[c+2], s2); atomicAdd(&s[c+3], s3);
    atomicAdd(&s[64+c+0], q0); atomicAdd(&s[64+c+1], q1);
    atomicAdd(&s[64+c+2], q2); atomicAdd(&s[64+c+3], q3);
    __syncthreads();
    for (int i = t; i < 128; i += 256) atomicAdd(&g_stats[i], s[i]);
}

__global__ void finalize2_kernel(const float* __restrict__ gamma, const float* __restrict__ beta) {
    int t = threadIdx.x;
    if (t < 64) {
        float inv = 1.0f / (float)NP;
        float m = g_stats[t] * inv;
        float v = g_stats[64 + t] * inv - m * m;
        float sc = rsqrtf(v + EPS) * gamma[t];
        g_scale[320 + t] = sc;
        g_shift[320 + t] = beta[t] - m * sc;
    }
}

// ---------------- compaction: per-offset (out, src) lists ----------------
__global__ __launch_bounds__(256) void compact_kernel(const int* __restrict__ nbrs) {
    __shared__ int scnt[8], sbase[8], woff[8][8];
    int t = threadIdx.x, w = t >> 5, lane = t & 31;
    if (t < 8) scnt[t] = 0;
    __syncthreads();
    int i = blockIdx.x * 256 + t;  // grid 3125 * 256 == NP
    int nb[8];
    {
        int kk = 0;
#pragma unroll
        for (int k = 0; k < 9; k++) {
            if (k == 4) continue;
            nb[kk++] = nbrs[i * 9 + k];
        }
    }
    unsigned ball[8];
#pragma unroll
    for (int k = 0; k < 8; k++) {
        unsigned m = __ballot_sync(0xffffffffu, nb[k] >= 0);
        ball[k] = m;
        if (lane == 0) woff[k][w] = atomicAdd(&scnt[k], __popc(m));
    }
    __syncthreads();
    if (t < 8) sbase[t] = atomicAdd(&g_cnt[t], scnt[t]);
    __syncthreads();
#pragma unroll
    for (int k = 0; k < 8; k++) {
        if (nb[k] >= 0) {
            int r = __popc(ball[k] & ((1u << lane) - 1u));
            g_list[k][sbase[k] + woff[k][w] + r] = make_int2(i, nb[k]);
        }
    }
}

// ---------------- conv center tap (2 rows/thread): Y2 = b2 + h1 @ w2[4] ----------------
__global__ __launch_bounds__(256, 1) void conv_center_kernel(
    const float* __restrict__ w2, const float* __restrict__ b2) {
    extern __shared__ float sm[];
    float* WT = sm;            // 64x64 transposed
    float* bias = sm + 4096;   // 64
    int t = threadIdx.x;
    for (int i = t; i < 4096; i += 256) {
        int c = i >> 6, j = i & 63;
        WT[i] = w2[4 * 4096 + j * 64 + c];
    }
    if (t < 64) bias[t] = b2[t];
    __syncthreads();

    int idx = blockIdx.x * 256 + t;
    if (idx >= HNP) return;
    long r0 = 2L * idx, r1 = r0 + 1;
    u64 xa[32], xb[32];
    load_row(g_h1 + r0 * 64, xa);
    load_row(g_h1 + r1 * 64, xb);
    float* ya = g_Y2 + r0 * 64;
    float* yb = g_Y2 + r1 * 64;
#pragma unroll 1
    for (int cq = 0; cq < 16; cq++) {
        int c = cq * 4;
        float4 ra, rb;
        dot4x2(WT, xa, xb, c, ra, rb);
        float4 bv = *(const float4*)(bias + c);
        ra.x += bv.x; ra.y += bv.y; ra.z += bv.z; ra.w += bv.w;
        rb.x += bv.x; rb.y += bv.y; rb.z += bv.z; rb.w += bv.w;
        *(float4*)(ya + c) = ra;
        *(float4*)(yb + c) = rb;
    }
}

// ---------------- conv non-center tap kk (2 entries/thread) ----------------
__global__ __launch_bounds__(256, 1) void convk_kernel(const float* __restrict__ w2, int kk) {
    extern __shared__ float sm[];
    float* WT = sm;           // 64x64 transposed
    int tap = (kk < 4) ? kk : kk + 1;
    int t = threadIdx.x;
    for (int i = t; i < 4096; i += 256) {
        int c = i >> 6, j = i & 63;
        WT[i] = w2[tap * 4096 + j * 64 + c];
    }
    __syncthreads();

    int n = g_cnt[kk];
    for (long e = ((long)blockIdx.x * 256 + t) * 2; e < n; e += (long)gridDim.x * 512) {
        int2 e0 = g_list[kk][e];
        bool two = (e + 1 < n);
        int2 e1 = two ? g_list[kk][e + 1] : e0;
        u64 xa[32], xb[32];
        load_row(g_h1 + (long)e0.y * 64, xa);
        load_row(g_h1 + (long)e1.y * 64, xb);
        float* ya = g_Y2 + (long)e0.x * 64;
        float* yb = g_Y2 + (long)e1.x * 64;
#pragma unroll 1
        for (int cq = 0; cq < 16; cq++) {
            int c = cq * 4;
            float4 ra, rb;
            dot4x2(WT, xa, xb, c, ra, rb);
            float4 y0 = *(float4*)(ya + c);
            y0.x += ra.x; y0.y += ra.y; y0.z += ra.z; y0.w += ra.w;
            *(float4*)(ya + c) = y0;
            if (two) {
                float4 y1 = *(float4*)(yb + c);
                y1.x += rb.x; y1.y += rb.y; y1.z += rb.z; y1.w += rb.w;
                *(float4*)(yb + c) = y1;
            }
        }
    }
}

// ---------------- GEMM3+final (2 rows/thread): out += relu(bn(bnrelu(Y2) @ w3)) ----------------
__global__ __launch_bounds__(256, 1) void gemm3_kernel(
    const float* __restrict__ w3, float* __restrict__ out) {
    extern __shared__ float sm[];
    float* WT  = sm;              // 256 cols x 64 transposed
    float* sc2 = sm + 16384;      // 64
    float* sh2 = sm + 16448;      // 64
    float* sc3 = sm + 16512;      // 256
    float* sh3 = sm + 16768;      // 256
    int t = threadIdx.x;
    for (int i = t; i < 16384; i += 256) {
        int c = i >> 6, j = i & 63;
        WT[i] = w3[j * 256 + c];
    }
    if (t < 64) { sc2[t] = g_scale[320 + t]; sh2[t] = g_shift[320 + t]; }
    for (int i = t; i < 256; i += 256) { sc3[i] = g_scale[384 + i]; sh3[i] = g_shift[384 + i]; }
    __syncthreads();

    int idx = blockIdx.x * 256 + t;
    if (idx >= HNP) return;
    long r0 = 2L * idx, r1 = r0 + 1;
    u64 xa[32], xb[32];
#pragma unroll
    for (int m = 0; m < 16; m++) {
        float4 s = *(const float4*)(sc2 + 4 * m);
        float4 h = *(const float4*)(sh2 + 4 * m);
        float4 v = *(const float4*)(g_Y2 + r0 * 64 + 4 * m);
        float x0 = fmaxf(fmaf(v.x, s.x, h.x), 0.f);
        float x1 = fmaxf(fmaf(v.y, s.y, h.y), 0.f);
        float x2 = fmaxf(fmaf(v.z, s.z, h.z), 0.f);
        float x3 = fmaxf(fmaf(v.w, s.w, h.w), 0.f);
        xa[2*m] = pack2(x0, x1); xa[2*m+1] = pack2(x2, x3);
        v = *(const float4*)(g_Y2 + r1 * 64 + 4 * m);
        x0 = fmaxf(fmaf(v.x, s.x, h.x), 0.f);
        x1 = fmaxf(fmaf(v.y, s.y, h.y), 0.f);
        x2 = fmaxf(fmaf(v.z, s.z, h.z), 0.f);
        x3 = fmaxf(fmaf(v.w, s.w, h.w), 0.f);
        xb[2*m] = pack2(x0, x1); xb[2*m+1] = pack2(x2, x3);
    }
    float* oa = out + r0 * 256;
    float* ob = out + r1 * 256;
#pragma unroll 1
    for (int cq = 0; cq < 64; cq++) {
        int c = cq * 4;
        float4 ra, rb;
        dot4x2(WT, xa, xb, c, ra, rb);
        float4 s = *(const float4*)(sc3 + c);
        float4 h = *(const float4*)(sh3 + c);
        float4 v = *(float4*)(oa + c);
        v.x += fmaxf(fmaf(ra.x, s.x, h.x), 0.f);
        v.y += fmaxf(fmaf(ra.y, s.y, h.y), 0.f);
        v.z += fmaxf(fmaf(ra.z, s.z, h.z), 0.f);
        v.w += fmaxf(fmaf(ra.w, s.w, h.w), 0.f);
        *(float4*)(oa + c) = v;
        v = *(float4*)(ob + c);
        v.x += fmaxf(fmaf(rb.x, s.x, h.x), 0.f);
        v.y += fmaxf(fmaf(rb.y, s.y, h.y), 0.f);
        v.z += fmaxf(fmaf(rb.z, s.z, h.z), 0.f);
        v.w += fmaxf(fmaf(rb.w, s.w, h.w), 0.f);
        *(float4*)(ob + c) = v;
    }
}

extern "C" void kernel_launch(void* const* d_in, const int* in_sizes, int n_in,
                              void* d_out, int out_size) {
    const float* feats = (const float*)d_in[0];
    const int*   nbrs  = (const int*)d_in[1];
    const float* w1  = (const float*)d_in[2];
    const float* g1  = (const float*)d_in[4];
    const float* be1 = (const float*)d_in[5];
    const float* w2  = (const float*)d_in[6];
    const float* b2  = (const float*)d_in[7];
    const float* g2  = (const float*)d_in[8];
    const float* be2 = (const float*)d_in[9];
    const float* w3  = (const float*)d_in[10];
    const float* g3  = (const float*)d_in[12];
    const float* be3 = (const float*)d_in[13];
    const float* wsp = (const float*)d_in[14];
    const float* gsp = (const float*)d_in[16];
    const float* besp= (const float*)d_in[17];
    float* out = (float*)d_out;

    cudaFuncSetAttribute(gemm1_kernel, cudaFuncAttributeMaxDynamicSharedMemorySize, 87040);
    cudaFuncSetAttribute(gemm3_kernel, cudaFuncAttributeMaxDynamicSharedMemorySize, 69632);

    zero_kernel<<<16, 256>>>(0);                               // 0
    syrk_kernel<<<250, 256>>>(feats, 0);                       // 1
    prep_dual_kernel<<<2, 256>>>(w1, g1, be1, wsp, gsp, besp); // 2
    gemm1_kernel<<<1563, 256, 87040>>>(feats, w1, wsp, out);   // 3  <- ncu capture slot
    compact_kernel<<<3125, 256>>>(nbrs);                       // 4
    conv_center_kernel<<<1563, 256, 16640>>>(w2, b2);          // 5
    for (int kk = 0; kk < 8; kk++)
        convk_kernel<<<592, 256, 16384>>>(w2, kk);             // 6..13
    stats2_kernel<<<1184, 256>>>();                            // 14
    finalize2_kernel<<<1, 64>>>(g2, be2);                      // 15
    zero_kernel<<<16, 256>>>(1);                               // 16
    syrk_kernel<<<250, 256>>>(nullptr, 1);                     // 17
    prep_kernel<<<1, 256>>>(w3, g3, be3, 256, 384);            // 18
    gemm3_kernel<<<1563, 256, 69632>>>(w3, out);               // 19
}

// round 6
// speedup vs baseline: 1.3611x; 1.0040x over previous
#include <cuda_runtime.h>

#define NP 800000
#define HNP 400000
#define EPS 1e-5f
typedef unsigned long long u64;

// ---------------- global scratch ----------------
__device__ float g_h1[(size_t)NP * 64];    // stage-1 POST bn+relu
__device__ float g_Y2[(size_t)NP * 64];    // conv pre-BN (raw)
__device__ int2  g_list[8][NP];            // per-offset compacted (out, src)
__device__ int   g_cnt[8];
__device__ float g_stats[128];             // Y2: sum[0,64) sq[64,128)
__device__ float g_C[4096];                // 64x64 second-moment (raw sums)
__device__ float g_Csum[64];               // column sums
// scale/shift: Y1 @0..64, YS @64..320, h2 @320..384, Y3 @384..640
__device__ float g_scale[640];
__device__ float g_shift[640];

// ---------------- f32x2 helpers ----------------
__device__ __forceinline__ void ffma2(u64 &acc, u64 x, u64 w) {
    asm("fma.rn.f32x2 %0, %1, %2, %0;" : "+l"(acc) : "l"(x), "l"(w));
}
__device__ __forceinline__ u64 pack2(float a, float b) {
    u64 r; asm("mov.b64 %0, {%1, %2};" : "=l"(r)
               : "r"(__float_as_uint(a)), "r"(__float_as_uint(b))); return r;
}
__device__ __forceinline__ u64 dup2(float v) {
    u64 r; asm("mov.b64 %0, {%1, %1};" : "=l"(r) : "r"(__float_as_uint(v))); return r;
}
__device__ __forceinline__ float2 unpack2(u64 v) {
    unsigned lo, hi; asm("mov.b64 {%0, %1}, %2;" : "=r"(lo), "=r"(hi) : "l"(v));
    return make_float2(__uint_as_float(lo), __uint_as_float(hi));
}

// 2-row x 4-col dot: weights loaded once, used for both rows.
// WT[c*64 + j] transposed; broadcast LDS.128 per 4 j's per column.
__device__ __forceinline__ void dot4x2(const float* __restrict__ WT,
                                       const u64* __restrict__ xa, const u64* __restrict__ xb,
                                       int c, float4& ra, float4& rb) {
    const ulonglong2* w0 = (const ulonglong2*)(WT + (c + 0) * 64);
    const ulonglong2* w1 = (const ulonglong2*)(WT + (c + 1) * 64);
    const ulonglong2* w2 = (const ulonglong2*)(WT + (c + 2) * 64);
    const ulonglong2* w3 = (const ulonglong2*)(WT + (c + 3) * 64);
    u64 a0 = 0, a1 = 0, a2 = 0, a3 = 0;
    u64 b0 = 0, b1 = 0, b2 = 0, b3 = 0;
#pragma unroll
    for (int m = 0; m < 16; m++) {
        ulonglong2 v0 = w0[m];
        ffma2(a0, xa[2*m], v0.x); ffma2(a0, xa[2*m+1], v0.y);
        ffma2(b0, xb[2*m], v0.x); ffma2(b0, xb[2*m+1], v0.y);
        ulonglong2 v1 = w1[m];
        ffma2(a1, xa[2*m], v1.x); ffma2(a1, xa[2*m+1], v1.y);
        ffma2(b1, xb[2*m], v1.x); ffma2(b1, xb[2*m+1], v1.y);
        ulonglong2 v2 = w2[m];
        ffma2(a2, xa[2*m], v2.x); ffma2(a2, xa[2*m+1], v2.y);
        ffma2(b2, xb[2*m], v2.x); ffma2(b2, xb[2*m+1], v2.y);
        ulonglong2 v3 = w3[m];
        ffma2(a3, xa[2*m], v3.x); ffma2(a3, xa[2*m+1], v3.y);
        ffma2(b3, xb[2*m], v3.x); ffma2(b3, xb[2*m+1], v3.y);
    }
    float2 p;
    p = unpack2(a0); ra.x = p.x + p.y;
    p = unpack2(a1); ra.y = p.x + p.y;
    p = unpack2(a2); ra.z = p.x + p.y;
    p = unpack2(a3); ra.w = p.x + p.y;
    p = unpack2(b0); rb.x = p.x + p.y;
    p = unpack2(b1); rb.y = p.x + p.y;
    p = unpack2(b2); rb.z = p.x + p.y;
    p = unpack2(b3); rb.w = p.x + p.y;
}

__device__ __forceinline__ void load_row(const float* __restrict__ row, u64* xp) {
    const ulonglong2* xr = (const ulonglong2*)row;
#pragma unroll
    for (int m = 0; m < 16; m++) { ulonglong2 v = xr[m]; xp[2*m] = v.x; xp[2*m+1] = v.y; }
}

__global__ void zero_kernel(int mode) {
    int i = blockIdx.x * blockDim.x + threadIdx.x;
    if (i < 4096) g_C[i] = 0.f;
    if (i < 64) g_Csum[i] = 0.f;
    if (mode == 0) {
        if (i < 128) g_stats[i] = 0.f;
        if (i < 8) g_cnt[i] = 0;
    }
}

// ---------------- SYRK: C += X^T X, Csum += colsums(X) ----------------
// which=0: X = Xin (feats). which=1: X = bnrelu(g_Y2) with scale/shift @320.
__global__ __launch_bounds__(256) void syrk_kernel(const float* __restrict__ Xin, int which) {
    __shared__ float tile[32 * 64];
    __shared__ float sc[64], sh[64];
    int t = threadIdx.x;
    if (which && t < 64) { sc[t] = g_scale[320 + t]; sh[t] = g_shift[320 + t]; }
    int ta = t >> 4, tb = t & 15;
    u64 acc[8] = {0,0,0,0,0,0,0,0};
    float cs0 = 0.f, cs1 = 0.f, cs2 = 0.f, cs3 = 0.f;
    const float4* src = (const float4*)(which ? (const float*)g_Y2 : Xin);
    long base16 = (long)blockIdx.x * 3200 * 16;

    for (int t0 = 0; t0 < 3200; t0 += 32) {
        __syncthreads();
        for (int i = t; i < 512; i += 256) {
            float4 v = src[base16 + (long)t0 * 16 + i];
            if (which) {
                int c0 = (i & 15) * 4;
                float4 s = *(const float4*)(sc + c0);
                float4 h = *(const float4*)(sh + c0);
                v.x = fmaxf(fmaf(v.x, s.x, h.x), 0.f);
                v.y = fmaxf(fmaf(v.y, s.y, h.y), 0.f);
                v.z = fmaxf(fmaf(v.z, s.z, h.z), 0.f);
                v.w = fmaxf(fmaf(v.w, s.w, h.w), 0.f);
            }
            *(float4*)(tile + i * 4) = v;
        }
        __syncthreads();
#pragma unroll 4
        for (int r = 0; r < 32; r++) {
            float4 xa = *(const float4*)(tile + r * 64 + ta * 4);
            float4 xb = *(const float4*)(tile + r * 64 + tb * 4);
            u64 b01 = pack2(xb.x, xb.y), b23 = pack2(xb.z, xb.w);
            u64 d;
            d = dup2(xa.x); ffma2(acc[0], d, b01); ffma2(acc[1], d, b23);
            d = dup2(xa.y); ffma2(acc[2], d, b01); ffma2(acc[3], d, b23);
            d = dup2(xa.z); ffma2(acc[4], d, b01); ffma2(acc[5], d, b23);
            d = dup2(xa.w); ffma2(acc[6], d, b01); ffma2(acc[7], d, b23);
            if (tb == 0) { cs0 += xa.x; cs1 += xa.y; cs2 += xa.z; cs3 += xa.w; }
        }
    }
#pragma unroll
    for (int a = 0; a < 4; a++) {
        float2 p0 = unpack2(acc[a * 2]), p1 = unpack2(acc[a * 2 + 1]);
        int row = ta * 4 + a;
        atomicAdd(&g_C[row * 64 + tb * 4 + 0], p0.x);
        atomicAdd(&g_C[row * 64 + tb * 4 + 1], p0.y);
        atomicAdd(&g_C[row * 64 + tb * 4 + 2], p1.x);
        atomicAdd(&g_C[row * 64 + tb * 4 + 3], p1.y);
    }
    if (tb == 0) {
        atomicAdd(&g_Csum[ta * 4 + 0], cs0);
        atomicAdd(&g_Csum[ta * 4 + 1], cs1);
        atomicAdd(&g_Csum[ta * 4 + 2], cs2);
        atomicAdd(&g_Csum[ta * 4 + 3], cs3);
    }
}

// ---------------- analytic BN params for y = x@W + b ----------------
__device__ __forceinline__ void prep_body(const float* __restrict__ W,
        const float* __restrict__ gamma, const float* __restrict__ beta,
        int ncols, int outOff) {
    __shared__ float Cs[4096];
    __shared__ float m[64];
    int t = threadIdx.x;
    float invN = 1.0f / (float)NP;
    for (int i = t; i < 4096; i += blockDim.x) Cs[i] = g_C[i] * invN;
    if (t < 64) m[t] = g_Csum[t] * invN;
    __syncthreads();
    if (t < ncols) {
        float w[64];
#pragma unroll
        for (int a = 0; a < 64; a++) w[a] = W[a * ncols + t];
        float mu = 0.f;
#pragma unroll
        for (int a = 0; a < 64; a++) mu = fmaf(m[a], w[a], mu);
        float q = 0.f;
#pragma unroll
        for (int a = 0; a < 64; a++) {
            const float* Cr = Cs + a * 64;
            float d0 = 0.f, d1 = 0.f, d2 = 0.f, d3 = 0.f;
#pragma unroll
            for (int b = 0; b < 64; b += 4) {
                d0 = fmaf(Cr[b + 0], w[b + 0], d0);
                d1 = fmaf(Cr[b + 1], w[b + 1], d1);
                d2 = fmaf(Cr[b + 2], w[b + 2], d2);
                d3 = fmaf(Cr[b + 3], w[b + 3], d3);
            }
            q = fmaf(w[a], (d0 + d1) + (d2 + d3), q);
        }
        float var = q - mu * mu;
        float scv = rsqrtf(var + EPS) * gamma[t];
        g_scale[outOff + t] = scv;
        g_shift[outOff + t] = beta[t] - mu * scv;
    }
}

// block 0: w1 (64 cols, outOff 0); block 1: ws (256 cols, outOff 64)
__global__ void prep_dual_kernel(const float* __restrict__ w1, const float* __restrict__ g1,
                                 const float* __restrict__ be1,
                                 const float* __restrict__ ws, const float* __restrict__ gs,
                                 const float* __restrict__ bes) {
    if (blockIdx.x == 0) prep_body(w1, g1, be1, 64, 0);
    else                 prep_body(ws, gs, bes, 256, 64);
}
__global__ void prep_kernel(const float* __restrict__ W, const float* __restrict__ gamma,
                            const float* __restrict__ beta, int ncols, int outOff) {
    prep_body(W, gamma, beta, ncols, outOff);
}

// ---------------- GEMM1 (2 rows/thread): h1 = relu(bn(feats@w1)); out = bn(feats@ws) ----------------
__global__ __launch_bounds__(256, 1) void gemm1_kernel(
    const float* __restrict__ feats, const float* __restrict__ w1,
    const float* __restrict__ ws, float* __restrict__ outYS) {
    extern __shared__ float sm[];
    float* WT = sm;               // 320 cols x 64 (transposed)
    float* scA = sm + 20480;      // 320
    float* shA = sm + 20800;      // 320
    int t = threadIdx.x;
    for (int i = t; i < 20480; i += 256) {
        int c = i >> 6, j = i & 63;
        WT[i] = (c < 64) ? w1[j * 64 + c] : ws[j * 256 + (c - 64)];
    }
    for (int i = t; i < 320; i += 256) { scA[i] = g_scale[i]; shA[i] = g_shift[i]; }
    __syncthreads();

    int idx = blockIdx.x * 256 + t;
    if (idx >= HNP) return;
    long r0 = 2L * idx, r1 = r0 + 1;
    u64 xa[32], xb[32];
    load_row(feats + r0 * 64, xa);
    load_row(feats + r1 * 64, xb);
    float* h1a = g_h1 + r0 * 64;  float* h1b = g_h1 + r1 * 64;
    float* ysa = outYS + r0 * 256; float* ysb = outYS + r1 * 256;
#pragma unroll 1
    for (int cq = 0; cq < 80; cq++) {
        int c = cq * 4;
        float4 ra, rb;
        dot4x2(WT, xa, xb, c, ra, rb);
        float4 s = *(const float4*)(scA + c);
        float4 h = *(const float4*)(shA + c);
        if (c < 64) {
            ra.x = fmaxf(fmaf(ra.x, s.x, h.x), 0.f); ra.y = fmaxf(fmaf(ra.y, s.y, h.y), 0.f);
            ra.z = fmaxf(fmaf(ra.z, s.z, h.z), 0.f); ra.w = fmaxf(fmaf(ra.w, s.w, h.w), 0.f);
            rb.x = fmaxf(fmaf(rb.x, s.x, h.x), 0.f); rb.y = fmaxf(fmaf(rb.y, s.y, h.y), 0.f);
            rb.z = fmaxf(fmaf(rb.z, s.z, h.z), 0.f); rb.w = fmaxf(fmaf(rb.w, s.w, h.w), 0.f);
            *(float4*)(h1a + c) = ra;
            *(float4*)(h1b + c) = rb;
        } else {
            ra.x = fmaf(ra.x, s.x, h.x); ra.y = fmaf(ra.y, s.y, h.y);
            ra.z = fmaf(ra.z, s.z, h.z); ra.w = fmaf(ra.w, s.w, h.w);
            rb.x = fmaf(rb.x, s.x, h.x); rb.y = fmaf(rb.y, s.y, h.y);
            rb.z = fmaf(rb.z, s.z, h.z); rb.w = fmaf(rb.w, s.w, h.w);
            *(float4*)(ysa + (c - 64)) = ra;
            *(float4*)(ysb + (c - 64)) = rb;
        }
    }
}

// ---------------- direct column stats for Y2 ----------------
__global__ __launch_bounds__(256) void stats2_kernel() {
    __shared__ float s[128];
    int t = threadIdx.x;
    for (int i = t; i < 128; i += 256) s[i] = 0.f;
    __syncthreads();
    int cg = t & 15;
    long r = (long)blockIdx.x * 16 + (t >> 4);
    long stride = (long)gridDim.x * 16;
    float s0=0,s1=0,s2=0,s3=0,q0=0,q1=0,q2=0,q3=0;
    for (; r < NP; r += stride) {
        float4 v = *(const float4*)(g_Y2 + r * 64 + cg * 4);
        s0 += v.x; q0 = fmaf(v.x, v.x, q0);
        s1 += v.y; q1 = fmaf(v.y, v.y, q1);
        s2 += v.z; q2 = fmaf(v.z, v.z, q2);
        s3 += v.w; q3 = fmaf(v.w, v.w, q3);
    }
    int c = cg * 4;
    atomicAdd(&s[c+0], s0); atomicAdd(&s[c+1], s1);
    atomicAdd(&s[c+2], s2); atomicAdd(&s[c+3], s3);
    atomicAdd(&s[64+c+0], q0); atomicAdd(&s[64+c+1], q1);
    atomicAdd(&s[64+c+2], q2); atomicAdd(&s[64+c+3], q3);
    __syncthreads();
    for (int i = t; i < 128; i += 256) atomicAdd(&g_stats[i], s[i]);
}

__global__ void finalize2_kernel(const float* __restrict__ gamma, const float* __restrict__ beta) {
    int t = threadIdx.x;
    if (t < 64) {
        float inv = 1.0f / (float)NP;
        float m = g_stats[t] * inv;
        float v = g_stats[64 + t] * inv - m * m;
        float sc = rsqrtf(v + EPS) * gamma[t];
        g_scale[320 + t] = sc;
        g_shift[320 + t] = beta[t] - m * sc;
    }
}

// ---------------- compaction: per-offset (out, src) lists ----------------
__global__ __launch_bounds__(256) void compact_kernel(const int* __restrict__ nbrs) {
    __shared__ int scnt[8], sbase[8], woff[8][8];
    int t = threadIdx.x, w = t >> 5, lane = t & 31;
    if (t < 8) scnt[t] = 0;
    __syncthreads();
    int i = blockIdx.x * 256 + t;  // grid 3125 * 256 == NP
    int nb[8];
    {
        int kk = 0;
#pragma unroll
        for (int k = 0; k < 9; k++) {
            if (k == 4) continue;
            nb[kk++] = nbrs[i * 9 + k];
        }
    }
    unsigned ball[8];
#pragma unroll
    for (int k = 0; k < 8; k++) {
        unsigned m = __ballot_sync(0xffffffffu, nb[k] >= 0);
        ball[k] = m;
        if (lane == 0) woff[k][w] = atomicAdd(&scnt[k], __popc(m));
    }
    __syncthreads();
    if (t < 8) sbase[t] = atomicAdd(&g_cnt[t], scnt[t]);
    __syncthreads();
#pragma unroll
    for (int k = 0; k < 8; k++) {
        if (nb[k] >= 0) {
            int r = __popc(ball[k] & ((1u << lane) - 1u));
            g_list[k][sbase[k] + woff[k][w] + r] = make_int2(i, nb[k]);
        }
    }
}

// ---------------- conv center tap (2 rows/thread): Y2 = b2 + h1 @ w2[4] ----------------
__global__ __launch_bounds__(256, 1) void conv_center_kernel(
    const float* __restrict__ w2, const float* __restrict__ b2) {
    extern __shared__ float sm[];
    float* WT = sm;            // 64x64 transposed
    float* bias = sm + 4096;   // 64
    int t = threadIdx.x;
    for (int i = t; i < 4096; i += 256) {
        int c = i >> 6, j = i & 63;
        WT[i] = w2[4 * 4096 + j * 64 + c];
    }
    if (t < 64) bias[t] = b2[t];
    __syncthreads();

    int idx = blockIdx.x * 256 + t;
    if (idx >= HNP) return;
    long r0 = 2L * idx, r1 = r0 + 1;
    u64 xa[32], xb[32];
    load_row(g_h1 + r0 * 64, xa);
    load_row(g_h1 + r1 * 64, xb);
    float* ya = g_Y2 + r0 * 64;
    float* yb = g_Y2 + r1 * 64;
#pragma unroll 1
    for (int cq = 0; cq < 16; cq++) {
        int c = cq * 4;
        float4 ra, rb;
        dot4x2(WT, xa, xb, c, ra, rb);
        float4 bv = *(const float4*)(bias + c);
        ra.x += bv.x; ra.y += bv.y; ra.z += bv.z; ra.w += bv.w;
        rb.x += bv.x; rb.y += bv.y; rb.z += bv.z; rb.w += bv.w;
        *(float4*)(ya + c) = ra;
        *(float4*)(yb + c) = rb;
    }
}

// ---------------- conv non-center tap kk (2 entries/thread) ----------------
__global__ __launch_bounds__(256, 1) void convk_kernel(const float* __restrict__ w2, int kk) {
    extern __shared__ float sm[];
    float* WT = sm;           // 64x64 transposed
    int tap = (kk < 4) ? kk : kk + 1;
    int t = threadIdx.x;
    for (int i = t; i < 4096; i += 256) {
        int c = i >> 6, j = i & 63;
        WT[i] = w2[tap * 4096 + j * 64 + c];
    }
    __syncthreads();

    int n = g_cnt[kk];
    for (long e = ((long)blockIdx.x * 256 + t) * 2; e < n; e += (long)gridDim.x * 512) {
        int2 e0 = g_list[kk][e];
        bool two = (e + 1 < n);
        int2 e1 = two ? g_list[kk][e + 1] : e0;
        u64 xa[32], xb[32];
        load_row(g_h1 + (long)e0.y * 64, xa);
        load_row(g_h1 + (long)e1.y * 64, xb);
        float* ya = g_Y2 + (long)e0.x * 64;
        float* yb = g_Y2 + (long)e1.x * 64;
#pragma unroll 1
        for (int cq = 0; cq < 16; cq++) {
            int c = cq * 4;
            float4 ra, rb;
            dot4x2(WT, xa, xb, c, ra, rb);
            float4 y0 = *(float4*)(ya + c);
            y0.x += ra.x; y0.y += ra.y; y0.z += ra.z; y0.w += ra.w;
            *(float4*)(ya + c) = y0;
            if (two) {
                float4 y1 = *(float4*)(yb + c);
                y1.x += rb.x; y1.y += rb.y; y1.z += rb.z; y1.w += rb.w;
                *(float4*)(yb + c) = y1;
            }
        }
    }
}

// ---------------- GEMM3+final (2 rows/thread): out += relu(bn(bnrelu(Y2) @ w3)) ----------------
__global__ __launch_bounds__(256, 1) void gemm3_kernel(
    const float* __restrict__ w3, float* __restrict__ out) {
    extern __shared__ float sm[];
    float* WT  = sm;              // 256 cols x 64 transposed
    float* sc2 = sm + 16384;      // 64
    float* sh2 = sm + 16448;      // 64
    float* sc3 = sm + 16512;      // 256
    float* sh3 = sm + 16768;      // 256
    int t = threadIdx.x;
    for (int i = t; i < 16384; i += 256) {
        int c = i >> 6, j = i & 63;
        WT[i] = w3[j * 256 + c];
    }
    if (t < 64) { sc2[t] = g_scale[320 + t]; sh2[t] = g_shift[320 + t]; }
    for (int i = t; i < 256; i += 256) { sc3[i] = g_scale[384 + i]; sh3[i] = g_shift[384 + i]; }
    __syncthreads();

    int idx = blockIdx.x * 256 + t;
    if (idx >= HNP) return;
    long r0 = 2L * idx, r1 = r0 + 1;
    u64 xa[32], xb[32];
#pragma unroll
    for (int m = 0; m < 16; m++) {
        float4 s = *(const float4*)(sc2 + 4 * m);
        float4 h = *(const float4*)(sh2 + 4 * m);
        float4 v = *(const float4*)(g_Y2 + r0 * 64 + 4 * m);
        float x0 = fmaxf(fmaf(v.x, s.x, h.x), 0.f);
        float x1 = fmaxf(fmaf(v.y, s.y, h.y), 0.f);
        float x2 = fmaxf(fmaf(v.z, s.z, h.z), 0.f);
        float x3 = fmaxf(fmaf(v.w, s.w, h.w), 0.f);
        xa[2*m] = pack2(x0, x1); xa[2*m+1] = pack2(x2, x3);
        v = *(const float4*)(g_Y2 + r1 * 64 + 4 * m);
        x0 = fmaxf(fmaf(v.x, s.x, h.x), 0.f);
        x1 = fmaxf(fmaf(v.y, s.y, h.y), 0.f);
        x2 = fmaxf(fmaf(v.z, s.z, h.z), 0.f);
        x3 = fmaxf(fmaf(v.w, s.w, h.w), 0.f);
        xb[2*m] = pack2(x0, x1); xb[2*m+1] = pack2(x2, x3);
    }
    float* oa = out + r0 * 256;
    float* ob = out + r1 * 256;
#pragma unroll 1
    for (int cq = 0; cq < 64; cq++) {
        int c = cq * 4;
        float4 ra, rb;
        dot4x2(WT, xa, xb, c, ra, rb);
        float4 s = *(const float4*)(sc3 + c);
        float4 h = *(const float4*)(sh3 + c);
        float4 v = *(float4*)(oa + c);
        v.x += fmaxf(fmaf(ra.x, s.x, h.x), 0.f);
        v.y += fmaxf(fmaf(ra.y, s.y, h.y), 0.f);
        v.z += fmaxf(fmaf(ra.z, s.z, h.z), 0.f);
        v.w += fmaxf(fmaf(ra.w, s.w, h.w), 0.f);
        *(float4*)(oa + c) = v;
        v = *(float4*)(ob + c);
        v.x += fmaxf(fmaf(rb.x, s.x, h.x), 0.f);
        v.y += fmaxf(fmaf(rb.y, s.y, h.y), 0.f);
        v.z += fmaxf(fmaf(rb.z, s.z, h.z), 0.f);
        v.w += fmaxf(fmaf(rb.w, s.w, h.w), 0.f);
        *(float4*)(ob + c) = v;
    }
}

extern "C" void kernel_launch(void* const* d_in, const int* in_sizes, int n_in,
                              void* d_out, int out_size) {
    const float* feats = (const float*)d_in[0];
    const int*   nbrs  = (const int*)d_in[1];
    const float* w1  = (const float*)d_in[2];
    const float* g1  = (const float*)d_in[4];
    const float* be1 = (const float*)d_in[5];
    const float* w2  = (const float*)d_in[6];
    const float* b2  = (const float*)d_in[7];
    const float* g2  = (const float*)d_in[8];
    const float* be2 = (const float*)d_in[9];
    const float* w3  = (const float*)d_in[10];
    const float* g3  = (const float*)d_in[12];
    const float* be3 = (const float*)d_in[13];
    const float* wsp = (const float*)d_in[14];
    const float* gsp = (const float*)d_in[16];
    const float* besp= (const float*)d_in[17];
    float* out = (float*)d_out;

    cudaFuncSetAttribute(gemm1_kernel, cudaFuncAttributeMaxDynamicSharedMemorySize, 87040);
    cudaFuncSetAttribute(gemm3_kernel, cudaFuncAttributeMaxDynamicSharedMemorySize, 69632);

    zero_kernel<<<16, 256>>>(0);                               // 0
    syrk_kernel<<<250, 256>>>(feats, 0);                       // 1
    prep_dual_kernel<<<2, 256>>>(w1, g1, be1, wsp, gsp, besp); // 2
    gemm1_kernel<<<1563, 256, 87040>>>(feats, w1, wsp, out);   // 3  <- ncu capture slot
    compact_kernel<<<3125, 256>>>(nbrs);                       // 4
    conv_center_kernel<<<1563, 256, 16640>>>(w2, b2);          // 5
    for (int kk = 0; kk < 8; kk++)
        convk_kernel<<<592, 256, 16384>>>(w2, kk);             // 6..13
    stats2_kernel<<<1184, 256>>>();                            // 14
    finalize2_kernel<<<1, 64>>>(g2, be2);                      // 15
    zero_kernel<<<16, 256>>>(1);                               // 16
    syrk_kernel<<<250, 256>>>(nullptr, 1);                     // 17
    prep_kernel<<<1, 256>>>(w3, g3, be3, 256, 384);            // 18
    gemm3_kernel<<<1563, 256, 69632>>>(w3, out);               // 19
}